// round 1
// baseline (speedup 1.0000x reference)
#include <cuda_runtime.h>
#include <cuda_bf16.h>
#include <math.h>

#define NA    900
#define NTEMP 600
#define ED    256
#define NC    6
#define NL    4
#define NP    13
#define NG    8
#define NLEARN 6
#define NDEC  6
#define ADIM  11
#define NCLS  10
#define WTOT  (NC*NL*NP*NG)   // 2496
#define NSEL  (NA-NTEMP)      // 300

// -------- output layout (flattened tuple, float32) --------
#define OFF_INST   0
#define OFF_ANCHOR (NA*ED)                       // 230400
#define OFF_CLS    (OFF_ANCHOR + NA*ADIM)        // 240300
#define OFF_QT     (OFF_CLS + NA*NCLS)           // 249300
#define OFF_TRACK  (OFF_QT + NA)                 // 250200
#define OFF_TMP    (OFF_TRACK + NA)              // 251100, + i*NA*ED

// -------- scratch (device globals; no runtime allocation) --------
__device__ __align__(16) float g_instA[NA*ED];
__device__ __align__(16) float g_instB[NA*ED];
__device__ __align__(16) float g_anchorA[NA*ADIM];
__device__ __align__(16) float g_anchorB[NA*ADIM];
__device__ __align__(16) float g_embed[NA*ED];
__device__ __align__(16) float g_uv[NA*NP*NC*2];
__device__ __align__(16) float g_W[NA*WTOT];
__device__ __align__(16) float g_cls[NA*NCLS];
__device__ int g_sel[NA];

__constant__ float c_FIX[7][3] = {
    {0.f,0.f,0.f},{0.5f,0.f,0.f},{-0.5f,0.f,0.f},
    {0.f,0.5f,0.f},{0.f,-0.5f,0.f},{0.f,0.f,0.5f},{0.f,0.f,-0.5f}};

// ===================== init: copy inputs into scratch =====================
__global__ void k_init(const float* __restrict__ inst_in,
                       const float* __restrict__ anchor_in)
{
    int i = blockIdx.x*blockDim.x + threadIdx.x;
    if (i < NA*ED)   g_instA[i]   = inst_in[i];
    if (i < NA*ADIM) g_anchorA[i] = anchor_in[i];
}

// ===================== k1: anchor embed + keypoints + projection ==========
__global__ void k1_embed_kps_proj(const float* __restrict__ anchor_w,
                                  const float* __restrict__ anchor_b,
                                  const float* __restrict__ kps_w,   // [256,18]
                                  const float* __restrict__ kps_b,   // [18]
                                  const float* __restrict__ l2i,     // [6,4,4]
                                  const float* __restrict__ image_wh,// [6,2]
                                  int use_b)
{
    int a = blockIdx.x, t = threadIdx.x;
    const float* inst = use_b ? g_instB : g_instA;
    const float* anch = use_b ? g_anchorB : g_anchorA;

    __shared__ float sfeat[ED];
    __shared__ float sanchor[ADIM];
    __shared__ float spart[18][8];
    __shared__ float slearn[18];
    __shared__ float skp[NP][3];

    sfeat[t] = inst[a*ED + t];
    if (t < ADIM) sanchor[t] = anch[a*ADIM + t];
    __syncthreads();

    // anchor embedding (256 outputs)
    {
        float e = anchor_b[t];
        #pragma unroll
        for (int j = 0; j < ADIM; j++) e += sanchor[j] * anchor_w[j*ED + t];
        g_embed[a*ED + t] = e;
    }

    // learned keypoint offsets: feat @ kps_w (256->18), deterministic 2-phase reduce
    if (t < 144) {
        int m = t >> 3, seg = t & 7;
        float s = 0.f;
        int k0 = seg * 32;
        #pragma unroll 8
        for (int k = k0; k < k0+32; k++) s += sfeat[k] * kps_w[k*18 + m];
        spart[m][seg] = s;
    }
    __syncthreads();
    if (t < 18) {
        float s = kps_b[t];
        #pragma unroll
        for (int seg = 0; seg < 8; seg++) s += spart[t][seg];
        slearn[t] = s;
    }
    __syncthreads();

    // keypoints
    if (t < NP*3) {
        int p = t/3, d = t%3;
        float center = sanchor[d];
        float size   = expf(sanchor[3+d]);
        float v = (p < 7) ? c_FIX[p][d] : slearn[(p-7)*3 + d];
        skp[p][d] = center + v * size;
    }
    __syncthreads();

    // projection: 13 keypoints x 6 cams
    if (t < NP*NC) {
        int p = t / NC, c = t % NC;
        const float* L = &l2i[c*16];
        float kx = skp[p][0], ky = skp[p][1], kz = skp[p][2];
        float p0 = L[0]*kx + L[1]*ky + L[2]*kz  + L[3];
        float p1 = L[4]*kx + L[5]*ky + L[6]*kz  + L[7];
        float p2 = L[8]*kx + L[9]*ky + L[10]*kz + L[11];
        float z  = fmaxf(p2, 1e-5f);
        float u  = p0 / z / image_wh[c*2 + 0];
        float v  = p1 / z / image_wh[c*2 + 1];
        g_uv[((a*NP + p)*NC + c)*2 + 0] = u;
        g_uv[((a*NP + p)*NC + c)*2 + 1] = v;
    }
}

// ===================== k2: wfc GEMM (X = inst+embed) [900x256]@[256x2496] ==
#define BM 64
#define BN 64
#define BK 16
__global__ void k2_wfc_gemm(const float* __restrict__ Wm,
                            const float* __restrict__ bias,
                            int use_b)
{
    const float* inst = use_b ? g_instB : g_instA;
    __shared__ __align__(16) float As[BK][BM];
    __shared__ __align__(16) float Bs[BK][BN];

    int tid  = threadIdx.x;          // 256 threads
    int tRow = tid >> 4, tCol = tid & 15;
    int m0 = blockIdx.y * BM, n0 = blockIdx.x * BN;

    float acc[4][4];
    #pragma unroll
    for (int i = 0; i < 4; i++)
        #pragma unroll
        for (int j = 0; j < 4; j++) acc[i][j] = 0.f;

    int aRow = tid >> 2;        // 0..63
    int aCol = (tid & 3) * 4;   // 0,4,8,12
    int bRow = tid >> 4;        // 0..15
    int bCol = (tid & 15) * 4;  // 0..60

    for (int k0 = 0; k0 < ED; k0 += BK) {
        int gm = m0 + aRow;
        float4 av = make_float4(0.f,0.f,0.f,0.f);
        if (gm < NA) {
            float4 x = *(const float4*)&inst[gm*ED + k0 + aCol];
            float4 e = *(const float4*)&g_embed[gm*ED + k0 + aCol];
            av = make_float4(x.x+e.x, x.y+e.y, x.z+e.z, x.w+e.w);
        }
        As[aCol+0][aRow] = av.x;
        As[aCol+1][aRow] = av.y;
        As[aCol+2][aRow] = av.z;
        As[aCol+3][aRow] = av.w;

        float4 bv = *(const float4*)&Wm[(k0 + bRow)*WTOT + n0 + bCol];
        *(float4*)&Bs[bRow][bCol] = bv;
        __syncthreads();

        #pragma unroll
        for (int k = 0; k < BK; k++) {
            float ra[4], rb[4];
            #pragma unroll
            for (int i = 0; i < 4; i++) ra[i] = As[k][tRow*4 + i];
            #pragma unroll
            for (int j = 0; j < 4; j++) rb[j] = Bs[k][tCol*4 + j];
            #pragma unroll
            for (int i = 0; i < 4; i++)
                #pragma unroll
                for (int j = 0; j < 4; j++) acc[i][j] += ra[i]*rb[j];
        }
        __syncthreads();
    }

    #pragma unroll
    for (int i = 0; i < 4; i++) {
        int r = m0 + tRow*4 + i;
        if (r >= NA) continue;
        #pragma unroll
        for (int j = 0; j < 4; j++) {
            int c = n0 + tCol*4 + j;
            g_W[r*WTOT + c] = acc[i][j] + bias[c];
        }
    }
}

// ===================== k3: softmax over 312 (per group of 8) ==============
__global__ void k3_softmax()
{
    int a = blockIdx.x, t = threadIdx.x;
    int g = t >> 5, lane = t & 31;
    float* row = &g_W[a*WTOT];

    float vals[10];
    float mx = -1e30f;
    int cnt = 0;
    for (int j = lane; j < NC*NL*NP; j += 32) {
        float v = row[j*NG + g];
        vals[cnt++] = v;
        mx = fmaxf(mx, v);
    }
    #pragma unroll
    for (int o = 16; o; o >>= 1) mx = fmaxf(mx, __shfl_xor_sync(0xffffffffu, mx, o));
    float sum = 0.f;
    for (int i = 0; i < cnt; i++) { vals[i] = expf(vals[i] - mx); sum += vals[i]; }
    #pragma unroll
    for (int o = 16; o; o >>= 1) sum += __shfl_xor_sync(0xffffffffu, sum, o);
    cnt = 0;
    for (int j = lane; j < NC*NL*NP; j += 32) {
        row[j*NG + g] = vals[cnt++] / sum;
    }
}

// ===================== k4: deformable aggregation =========================
__global__ void k4_daf(const float* __restrict__ feature,
                       const int* __restrict__ ss,   // [4,2] (H,W)
                       const int* __restrict__ lsi,  // [4]
                       int T,
                       float* __restrict__ feats_out)
{
    int a = blockIdx.x, t = threadIdx.x, g = t >> 5;
    __shared__ float sW[WTOT];
    __shared__ float suv[NP*NC*2];
    __shared__ int   sh[12];

    for (int idx = t; idx < WTOT; idx += 256)    sW[idx]  = g_W[a*WTOT + idx];
    for (int idx = t; idx < NP*NC*2; idx += 256) suv[idx] = g_uv[a*NP*NC*2 + idx];
    if (t < 8) sh[t]   = ss[t];
    if (t < 4) sh[8+t] = lsi[t];
    __syncthreads();

    float acc = 0.f;
    #pragma unroll 1
    for (int l = 0; l < NL; l++) {
        int H = sh[l*2], Wd = sh[l*2 + 1], st = sh[8 + l];
        float fH = (float)H, fW = (float)Wd;
        #pragma unroll 1
        for (int p = 0; p < NP; p++) {
            #pragma unroll 1
            for (int c = 0; c < NC; c++) {
                float u = suv[(p*NC + c)*2 + 0];
                float v = suv[(p*NC + c)*2 + 1];
                float x = u*fW - 0.5f, y = v*fH - 0.5f;
                float x0 = floorf(x), y0 = floorf(y);
                float dx = x - x0,    dy = y - y0;
                float x1 = x0 + 1.f,  y1 = y0 + 1.f;
                float aw = sW[(c*52 + l*13 + p)*NG + g];
                int cbase = (c*T + st)*ED + t;

                bool vx0 = (x0 >= 0.f) && (x0 < fW);
                bool vx1 = (x1 >= 0.f) && (x1 < fW);
                bool vy0 = (y0 >= 0.f) && (y0 < fH);
                bool vy1 = (y1 >= 0.f) && (y1 < fH);

                float w00 = (1.f-dx)*(1.f-dy);
                if (vx0 && vy0 && w00 != 0.f)
                    acc += feature[cbase + ((int)y0*Wd + (int)x0)*ED] * (w00*aw);
                float w10 = dx*(1.f-dy);
                if (vx1 && vy0 && w10 != 0.f)
                    acc += feature[cbase + ((int)y0*Wd + (int)x1)*ED] * (w10*aw);
                float w01 = (1.f-dx)*dy;
                if (vx0 && vy1 && w01 != 0.f)
                    acc += feature[cbase + ((int)y1*Wd + (int)x0)*ED] * (w01*aw);
                float w11 = dx*dy;
                if (vx1 && vy1 && w11 != 0.f)
                    acc += feature[cbase + ((int)y1*Wd + (int)x1)*ED] * (w11*aw);
            }
        }
    }
    feats_out[a*ED + t] = acc;
}

// ===================== k5: outp -> ffn(relu) -> heads =====================
#define TR 8
__global__ void k5_tail(const float* __restrict__ feats,
                        const float* __restrict__ outp_w, const float* __restrict__ outp_b,
                        const float* __restrict__ ffn_w,  const float* __restrict__ ffn_b,
                        const float* __restrict__ reg_w,  const float* __restrict__ reg_b,
                        const float* __restrict__ cls_w,  const float* __restrict__ cls_b,
                        const float* __restrict__ qt_w,   const float* __restrict__ qt_b,
                        const float* __restrict__ time_interval,
                        int use_b, int cls_mode, float* cls_dst,
                        int qt_on, float* qt_dst)
{
    float* inst = use_b ? g_instB : g_instA;
    float* anch = use_b ? g_anchorB : g_anchorA;
    int t = threadIdx.x;
    int r0 = blockIdx.x * TR;

    __shared__ float sIn[TR*ED];        // feats, later new inst
    __shared__ float sCat[TR*2*ED];     // [out(256) | inst(256)] per row
    __shared__ float sHW[ED*ADIM + ED*NCLS + ED];  // reg_w | cls_w | qt_w

    for (int idx = t; idx < TR*ED; idx += 256) {
        int r = idx >> 8, col = idx & 255;
        int row = r0 + r;
        sIn[idx] = (row < NA) ? feats[row*ED + col] : 0.f;
        sCat[r*512 + 256 + col] = (row < NA) ? inst[row*ED + col] : 0.f;
    }
    for (int idx = t; idx < ED*ADIM; idx += 256) sHW[idx] = reg_w[idx];
    bool do_cls = (cls_mode != 0);
    if (do_cls)
        for (int idx = t; idx < ED*NCLS; idx += 256) sHW[ED*ADIM + idx] = cls_w[idx];
    if (qt_on)
        for (int idx = t; idx < ED; idx += 256) sHW[ED*ADIM + ED*NCLS + idx] = qt_w[idx];
    __syncthreads();

    // ---- out = feats @ outp_w + b ----
    float acc[TR];
    #pragma unroll
    for (int r = 0; r < TR; r++) acc[r] = 0.f;
    for (int k = 0; k < ED; k++) {
        float wv = outp_w[k*ED + t];
        #pragma unroll
        for (int r = 0; r < TR; r++) acc[r] += sIn[r*ED + k] * wv;
    }
    float ob = outp_b[t];
    #pragma unroll
    for (int r = 0; r < TR; r++) sCat[r*512 + t] = acc[r] + ob;
    __syncthreads();

    // ---- new_inst = relu(cat @ ffn_w + b) ----
    float acc2[TR];
    #pragma unroll
    for (int r = 0; r < TR; r++) acc2[r] = 0.f;
    for (int k = 0; k < 2*ED; k++) {
        float wv = ffn_w[k*ED + t];
        #pragma unroll
        for (int r = 0; r < TR; r++) acc2[r] += sCat[r*512 + k] * wv;
    }
    float fb = ffn_b[t];
    #pragma unroll
    for (int r = 0; r < TR; r++) {
        float nv = fmaxf(acc2[r] + fb, 0.f);
        sIn[r*ED + t] = nv;
        int row = r0 + r;
        if (row < NA) inst[row*ED + t] = nv;
    }
    __syncthreads();

    // ---- heads ----
    float ti = time_interval[0];
    for (int o = t; o < TR*ADIM; o += 256) {
        int r = o / ADIM, j = o % ADIM;
        int row = r0 + r;
        if (row < NA) {
            float s = reg_b[j];
            for (int k = 0; k < ED; k++) s += sIn[r*ED + k] * sHW[k*ADIM + j];
            if (j >= 8) s /= ti;
            anch[row*ADIM + j] += s;
        }
    }
    if (do_cls) {
        float* cdst = (cls_mode == 1) ? g_cls : cls_dst;
        for (int o = t; o < TR*NCLS; o += 256) {
            int r = o / NCLS, j = o % NCLS;
            int row = r0 + r;
            if (row < NA) {
                float s = cls_b[j];
                for (int k = 0; k < ED; k++) s += sIn[r*ED + k] * sHW[ED*ADIM + k*NCLS + j];
                cdst[row*NCLS + j] = s;
            }
        }
    }
    if (qt_on) {
        for (int o = t; o < TR; o += 256) {
            int row = r0 + o;
            if (row < NA) {
                float s = qt_b[0];
                for (int k = 0; k < ED; k++) s += sIn[o*ED + k] * sHW[ED*ADIM + ED*NCLS + k];
                qt_dst[row] = s;
            }
        }
    }
}

// ===================== rank (exact top-k by count) + gather ===============
__global__ void k_rank()
{
    __shared__ float ssc[NA];
    int t = threadIdx.x;
    if (t < NA) {
        float m = -1e30f;
        #pragma unroll
        for (int j = 0; j < NCLS; j++) m = fmaxf(m, g_cls[t*NCLS + j]);
        ssc[t] = m;
    }
    __syncthreads();
    if (t < NA) {
        float sc = ssc[t];
        int cnt = 0;
        for (int b = 0; b < NA; b++) {
            float sb = ssc[b];
            cnt += (sb > sc) || (sb == sc && b < t);
        }
        if (cnt < NSEL) g_sel[NTEMP + cnt] = t;
    }
}

__global__ void k_gather(const float* __restrict__ temp_inst,
                         const float* __restrict__ temp_anchor,
                         const unsigned char* __restrict__ mask)
{
    int r = blockIdx.x, t = threadIdx.x;
    bool m = mask[0] != 0;
    if (m) {
        if (r < NTEMP) {
            g_instB[r*ED + t] = temp_inst[r*ED + t];
            if (t < ADIM) g_anchorB[r*ADIM + t] = temp_anchor[r*ADIM + t];
        } else {
            int s = g_sel[r];
            g_instB[r*ED + t] = g_instA[s*ED + t];
            if (t < ADIM) g_anchorB[r*ADIM + t] = g_anchorA[s*ADIM + t];
        }
    } else {
        g_instB[r*ED + t] = g_instA[r*ED + t];
        if (t < ADIM) g_anchorB[r*ADIM + t] = g_anchorA[r*ADIM + t];
    }
}

// ===================== finalize ===========================================
__global__ void k_finalize(float* __restrict__ out,
                           const int* __restrict__ track_id,
                           const unsigned char* __restrict__ mask)
{
    int i = blockIdx.x*blockDim.x + threadIdx.x;
    if (i < NA*ED)   out[OFF_INST + i]   = g_instB[i];
    if (i < NA*ADIM) out[OFF_ANCHOR + i] = g_anchorB[i];
    if (i < NA) {
        bool m = mask[0] != 0;
        out[OFF_TRACK + i] = m ? (float)track_id[i] : -1.0f;
    }
}

// ===================== host ===============================================
extern "C" void kernel_launch(void* const* d_in, const int* in_sizes, int n_in,
                              void* d_out, int out_size)
{
    const float* feature      = (const float*)d_in[0];
    const int*   ss           = (const int*)d_in[1];
    const int*   lsi          = (const int*)d_in[2];
    const float* inst_in      = (const float*)d_in[3];
    const float* anchor_in    = (const float*)d_in[4];
    const float* ti           = (const float*)d_in[5];
    const float* temp_inst    = (const float*)d_in[6];
    const float* temp_anchor  = (const float*)d_in[7];
    const unsigned char* mask = (const unsigned char*)d_in[8];
    const int*   track_id     = (const int*)d_in[9];
    const float* image_wh     = (const float*)d_in[10];
    const float* l2i          = (const float*)d_in[11];
    const float* anchor_w     = (const float*)d_in[12];
    const float* anchor_b     = (const float*)d_in[13];
    const float* kps_w        = (const float*)d_in[14];
    const float* kps_b        = (const float*)d_in[15];
    const float* wfc_w        = (const float*)d_in[16];
    const float* wfc_b        = (const float*)d_in[17];
    const float* outp_w       = (const float*)d_in[18];
    const float* outp_b       = (const float*)d_in[19];
    const float* ffn_w        = (const float*)d_in[20];
    const float* ffn_b        = (const float*)d_in[21];
    const float* reg_w        = (const float*)d_in[22];
    const float* reg_b        = (const float*)d_in[23];
    const float* cls_w        = (const float*)d_in[24];
    const float* cls_b        = (const float*)d_in[25];
    const float* qt_w         = (const float*)d_in[26];
    const float* qt_b         = (const float*)d_in[27];

    int T = in_sizes[0] / (NC*ED);
    float* out = (float*)d_out;

    k_init<<<(NA*ED + 255)/256, 256>>>(inst_in, anchor_in);

    for (int i = 0; i < NDEC; i++) {
        int use_b = (i >= 1) ? 1 : 0;

        k1_embed_kps_proj<<<NA, 256>>>(anchor_w, anchor_b,
                                       kps_w + (size_t)i*ED*NLEARN*3,
                                       kps_b + (size_t)i*NLEARN*3,
                                       l2i, image_wh, use_b);

        dim3 g2(WTOT/BN, (NA + BM - 1)/BM);
        k2_wfc_gemm<<<g2, 256>>>(wfc_w + (size_t)i*ED*WTOT,
                                 wfc_b + (size_t)i*WTOT, use_b);

        k3_softmax<<<NA, 256>>>();

        float* feats = out + OFF_TMP + (size_t)i*NA*ED;
        k4_daf<<<NA, 256>>>(feature, ss, lsi, T, feats);

        int cls_mode = (i == 0) ? 1 : ((i == NDEC-1) ? 2 : 0);
        int qt_on    = (i == NDEC-1) ? 1 : 0;
        k5_tail<<<(NA + TR - 1)/TR, 256>>>(feats,
                    outp_w + (size_t)i*ED*ED,    outp_b + (size_t)i*ED,
                    ffn_w  + (size_t)i*2*ED*ED,  ffn_b  + (size_t)i*ED,
                    reg_w  + (size_t)i*ED*ADIM,  reg_b  + (size_t)i*ADIM,
                    cls_w  + (size_t)i*ED*NCLS,  cls_b  + (size_t)i*NCLS,
                    qt_w   + (size_t)i*ED,       qt_b   + (size_t)i,
                    ti, use_b, cls_mode, out + OFF_CLS, qt_on, out + OFF_QT);

        if (i == 0) {
            k_rank<<<1, 1024>>>();
            k_gather<<<NA, 256>>>(temp_inst, temp_anchor, mask);
        }
    }

    k_finalize<<<(NA*ED + 255)/256, 256>>>(out, track_id, mask);
}

// round 2
// speedup vs baseline: 1.9074x; 1.9074x over previous
#include <cuda_runtime.h>
#include <cuda_bf16.h>
#include <math.h>

#define NA    900
#define NTEMP 600
#define ED    256
#define NC    6
#define NL    4
#define NP    13
#define NG    8
#define NLEARN 6
#define NDEC  6
#define ADIM  11
#define NCLS  10
#define WTOT  (NC*NL*NP*NG)   // 2496
#define NSEL  (NA-NTEMP)      // 300
#define NITEM (NL*NP*NC)      // 312

typedef unsigned long long ull;

// -------- output layout (flattened tuple, float32) --------
#define OFF_INST   0
#define OFF_ANCHOR (NA*ED)
#define OFF_CLS    (OFF_ANCHOR + NA*ADIM)
#define OFF_QT     (OFF_CLS + NA*NCLS)
#define OFF_TRACK  (OFF_QT + NA)
#define OFF_TMP    (OFF_TRACK + NA)

// -------- scratch --------
__device__ __align__(16) float g_instA[NA*ED];
__device__ __align__(16) float g_instB[NA*ED];
__device__ __align__(16) float g_anchorA[NA*ADIM];
__device__ __align__(16) float g_anchorB[NA*ADIM];
__device__ __align__(16) float g_embed[NA*ED];
__device__ __align__(16) float g_uv[NA*NP*NC*2];
__device__ __align__(16) float g_W[NA*WTOT];
__device__ __align__(16) float g_cls[NA*NCLS];
__device__ int g_sel[NA];

__constant__ float c_FIX[7][3] = {
    {0.f,0.f,0.f},{0.5f,0.f,0.f},{-0.5f,0.f,0.f},
    {0.f,0.5f,0.f},{0.f,-0.5f,0.f},{0.f,0.f,0.5f},{0.f,0.f,-0.5f}};

// ---- f32x2 helpers (Blackwell packed fp32 FMA; bit-identical to scalar FFMA) ----
__device__ __forceinline__ ull pack2(float x, float y) {
    ull r;
    asm("mov.b64 %0, {%1, %2};" : "=l"(r) : "f"(x), "f"(y));
    return r;
}
__device__ __forceinline__ void unpack2(ull v, float& x, float& y) {
    asm("mov.b64 {%0, %1}, %2;" : "=f"(x), "=f"(y) : "l"(v));
}
__device__ __forceinline__ void ffma2(ull& acc, ull a, ull b) {
    asm("fma.rn.f32x2 %0, %1, %2, %0;" : "+l"(acc) : "l"(a), "l"(b));
}

// ===================== init =====================
__global__ void k_init(const float* __restrict__ inst_in,
                       const float* __restrict__ anchor_in)
{
    int i = blockIdx.x*blockDim.x + threadIdx.x;
    if (i < NA*ED)   g_instA[i]   = inst_in[i];
    if (i < NA*ADIM) g_anchorA[i] = anchor_in[i];
}

// ===================== k1: anchor embed + keypoints + projection ==========
__global__ void k1_embed_kps_proj(const float* __restrict__ anchor_w,
                                  const float* __restrict__ anchor_b,
                                  const float* __restrict__ kps_w,   // [256,18]
                                  const float* __restrict__ kps_b,   // [18]
                                  const float* __restrict__ l2i,     // [6,4,4]
                                  const float* __restrict__ image_wh,// [6,2]
                                  int use_b)
{
    int a = blockIdx.x, t = threadIdx.x;
    const float* inst = use_b ? g_instB : g_instA;
    const float* anch = use_b ? g_anchorB : g_anchorA;

    __shared__ float sfeat[ED];
    __shared__ float sanchor[ADIM];
    __shared__ float spart[18][8];
    __shared__ float slearn[18];
    __shared__ float skp[NP][3];

    sfeat[t] = inst[a*ED + t];
    if (t < ADIM) sanchor[t] = anch[a*ADIM + t];
    __syncthreads();

    {
        float e = anchor_b[t];
        #pragma unroll
        for (int j = 0; j < ADIM; j++) e += sanchor[j] * anchor_w[j*ED + t];
        g_embed[a*ED + t] = e;
    }

    if (t < 144) {
        int m = t >> 3, seg = t & 7;
        float s = 0.f;
        int k0 = seg * 32;
        #pragma unroll 8
        for (int k = k0; k < k0+32; k++) s += sfeat[k] * kps_w[k*18 + m];
        spart[m][seg] = s;
    }
    __syncthreads();
    if (t < 18) {
        float s = kps_b[t];
        #pragma unroll
        for (int seg = 0; seg < 8; seg++) s += spart[t][seg];
        slearn[t] = s;
    }
    __syncthreads();

    if (t < NP*3) {
        int p = t/3, d = t%3;
        float center = sanchor[d];
        float size   = expf(sanchor[3+d]);
        float v = (p < 7) ? c_FIX[p][d] : slearn[(p-7)*3 + d];
        skp[p][d] = center + v * size;
    }
    __syncthreads();

    if (t < NP*NC) {
        int p = t / NC, c = t % NC;
        const float* L = &l2i[c*16];
        float kx = skp[p][0], ky = skp[p][1], kz = skp[p][2];
        float p0 = L[0]*kx + L[1]*ky + L[2]*kz  + L[3];
        float p1 = L[4]*kx + L[5]*ky + L[6]*kz  + L[7];
        float p2 = L[8]*kx + L[9]*ky + L[10]*kz + L[11];
        float z  = fmaxf(p2, 1e-5f);
        float u  = p0 / z / image_wh[c*2 + 0];
        float v  = p1 / z / image_wh[c*2 + 1];
        g_uv[((a*NP + p)*NC + c)*2 + 0] = u;
        g_uv[((a*NP + p)*NC + c)*2 + 1] = v;
    }
}

// ===================== k2: wfc GEMM, f32x2 micro-kernel ====================
// [900x256] @ [256x2496], BM=64 BN=96 BK=16, 256 thr, 4x6 per thread
#define BM 64
#define BN 96
#define BK 16
__global__ void k2_wfc_gemm(const float* __restrict__ Wm,
                            const float* __restrict__ bias,
                            int use_b)
{
    const float* inst = use_b ? g_instB : g_instA;
    __shared__ __align__(16) float As[BM][BK];   // m-major
    __shared__ __align__(16) float Bs[BK][BN];   // n contiguous

    int tid  = threadIdx.x;
    int tRow = tid >> 4, tCol = tid & 15;        // 16x16
    int m0 = blockIdx.y * BM, n0 = blockIdx.x * BN;

    ull acc[4][3];
    #pragma unroll
    for (int i = 0; i < 4; i++)
        #pragma unroll
        for (int j = 0; j < 3; j++) acc[i][j] = 0ull;

    int aRow = tid >> 2;         // 0..63
    int aK4  = (tid & 3) * 4;    // 0,4,8,12

    for (int k0 = 0; k0 < ED; k0 += BK) {
        int gm = m0 + aRow;
        float4 av = make_float4(0.f,0.f,0.f,0.f);
        if (gm < NA) {
            float4 x = *(const float4*)&inst[gm*ED + k0 + aK4];
            float4 e = *(const float4*)&g_embed[gm*ED + k0 + aK4];
            av = make_float4(x.x+e.x, x.y+e.y, x.z+e.z, x.w+e.w);
        }
        *(float4*)&As[aRow][aK4] = av;

        #pragma unroll
        for (int it = 0; it < 3; it++) {
            int lin = tid + it*256;      // 0..767 (16 rows x 48 float2)
            int r = lin / 48, c2 = lin % 48;
            *(float2*)&Bs[r][c2*2] =
                *(const float2*)&Wm[(size_t)(k0 + r)*WTOT + n0 + c2*2];
        }
        __syncthreads();

        #pragma unroll
        for (int k = 0; k < BK; k++) {
            ull b0 = *(const ull*)&Bs[k][tCol*6 + 0];
            ull b1 = *(const ull*)&Bs[k][tCol*6 + 2];
            ull b2 = *(const ull*)&Bs[k][tCol*6 + 4];
            #pragma unroll
            for (int i = 0; i < 4; i++) {
                float a = As[tRow*4 + i][k];
                ull ad = pack2(a, a);
                ffma2(acc[i][0], ad, b0);
                ffma2(acc[i][1], ad, b1);
                ffma2(acc[i][2], ad, b2);
            }
        }
        __syncthreads();
    }

    float2 bb[3];
    #pragma unroll
    for (int j = 0; j < 3; j++)
        bb[j] = *(const float2*)&bias[n0 + tCol*6 + 2*j];

    #pragma unroll
    for (int i = 0; i < 4; i++) {
        int r = m0 + tRow*4 + i;
        if (r >= NA) continue;
        #pragma unroll
        for (int j = 0; j < 3; j++) {
            float x, y;
            unpack2(acc[i][j], x, y);
            float2 v = make_float2(x + bb[j].x, y + bb[j].y);
            *(float2*)&g_W[(size_t)r*WTOT + n0 + tCol*6 + 2*j] = v;
        }
    }
}

// ===================== k4: fused softmax + deformable aggregation =========
__global__ void k4_daf(const float* __restrict__ feature,
                       const int* __restrict__ ss,
                       const int* __restrict__ lsi,
                       int T,
                       float* __restrict__ feats_out)
{
    int a = blockIdx.x, t = threadIdx.x, g = t >> 5, lane = t & 31;
    __shared__ float sW[WTOT];
    __shared__ float suv[NP*NC*2];
    __shared__ int   sh[12];
    __shared__ int   sBase[NITEM];
    __shared__ int   sWi[NITEM];        // pre-multiplied weight index (*NG)
    __shared__ int4  sOff[NITEM];
    __shared__ float4 sCw[NITEM];

    for (int idx = t; idx < WTOT; idx += 256)    sW[idx]  = g_W[(size_t)a*WTOT + idx];
    for (int idx = t; idx < NP*NC*2; idx += 256) suv[idx] = g_uv[a*NP*NC*2 + idx];
    if (t < 8) sh[t]   = ss[t];
    if (t < 4) sh[8+t] = lsi[t];
    __syncthreads();

    // ---- softmax over 312 entries of group g (warp per group) ----
    {
        float vals[10];
        float mx = -1e30f;
        int cnt = 0;
        for (int j = lane; j < NITEM; j += 32) {
            float v = sW[j*NG + g];
            vals[cnt++] = v;
            mx = fmaxf(mx, v);
        }
        #pragma unroll
        for (int o = 16; o; o >>= 1) mx = fmaxf(mx, __shfl_xor_sync(0xffffffffu, mx, o));
        float sum = 0.f;
        for (int i = 0; i < cnt; i++) { vals[i] = expf(vals[i] - mx); sum += vals[i]; }
        #pragma unroll
        for (int o = 16; o; o >>= 1) sum += __shfl_xor_sync(0xffffffffu, sum, o);
        float inv = 1.f / sum;
        cnt = 0;
        for (int j = lane; j < NITEM; j += 32)
            sW[j*NG + g] = vals[cnt++] * inv;
    }

    // ---- precompute per-item offsets/weights (shared by all 256 threads) ----
    for (int i = t; i < NITEM; i += 256) {
        int c  = i % NC;
        int lp = i / NC;
        int p  = lp % NP;
        int l  = lp / NP;
        int H = sh[l*2], Wd = sh[l*2+1], st = sh[8+l];
        float fH = (float)H, fW = (float)Wd;
        float u = suv[(p*NC + c)*2 + 0];
        float v = suv[(p*NC + c)*2 + 1];
        float x = u*fW - 0.5f, y = v*fH - 0.5f;
        float x0f = floorf(x), y0f = floorf(y);
        float dx = x - x0f, dy = y - y0f;
        float x1f = x0f + 1.f, y1f = y0f + 1.f;
        bool vx0 = (x0f >= 0.f) && (x0f < fW);
        bool vx1 = (x1f >= 0.f) && (x1f < fW);
        bool vy0 = (y0f >= 0.f) && (y0f < fH);
        bool vy1 = (y1f >= 0.f) && (y1f < fH);
        int x0 = vx0 ? (int)x0f : 0;
        int x1 = vx1 ? (int)x1f : 0;
        int y0 = vy0 ? (int)y0f : 0;
        int y1 = vy1 ? (int)y1f : 0;

        float4 w;
        w.x = (vx0 && vy0) ? (1.f-dx)*(1.f-dy) : 0.f;
        w.y = (vx1 && vy0) ? dx*(1.f-dy)       : 0.f;
        w.z = (vx0 && vy1) ? (1.f-dx)*dy       : 0.f;
        w.w = (vx1 && vy1) ? dx*dy             : 0.f;
        int4 o;
        o.x = (y0*Wd + x0)*ED;
        o.y = (y0*Wd + x1)*ED;
        o.z = (y1*Wd + x0)*ED;
        o.w = (y1*Wd + x1)*ED;

        bool any = (w.x != 0.f) | (w.y != 0.f) | (w.z != 0.f) | (w.w != 0.f);
        sBase[i] = any ? (c*T + st)*ED : -1;
        sWi[i]   = (c*52 + l*13 + p)*NG;
        sOff[i]  = o;
        sCw[i]   = w;
    }
    __syncthreads();

    // ---- main aggregation loop (block-uniform branches) ----
    float acc = 0.f;
    for (int i = 0; i < NITEM; i++) {
        int base = sBase[i];
        if (base < 0) continue;
        float aw = sW[sWi[i] + g];
        const float* f = feature + base + t;
        float4 w = sCw[i];
        int4  o = sOff[i];
        if (w.x != 0.f) acc += f[o.x] * (w.x * aw);
        if (w.y != 0.f) acc += f[o.y] * (w.y * aw);
        if (w.z != 0.f) acc += f[o.z] * (w.z * aw);
        if (w.w != 0.f) acc += f[o.w] * (w.w * aw);
    }
    feats_out[a*ED + t] = acc;
}

// ===================== k5: outp -> ffn(relu) -> heads (f32x2 pairs) =======
#define TR 8
#define TP 10   // pad: 8B-aligned row-pair LDS.64 + low STS conflicts
__global__ void k5_tail(const float* __restrict__ feats,
                        const float* __restrict__ outp_w, const float* __restrict__ outp_b,
                        const float* __restrict__ ffn_w,  const float* __restrict__ ffn_b,
                        const float* __restrict__ reg_w,  const float* __restrict__ reg_b,
                        const float* __restrict__ cls_w,  const float* __restrict__ cls_b,
                        const float* __restrict__ qt_w,   const float* __restrict__ qt_b,
                        const float* __restrict__ time_interval,
                        int use_b, int cls_mode, float* cls_dst,
                        int qt_on, float* qt_dst)
{
    float* inst = use_b ? g_instB : g_instA;
    float* anch = use_b ? g_anchorB : g_anchorA;
    int t = threadIdx.x;
    int r0 = blockIdx.x * TR;

    __shared__ __align__(8) float bufA[ED][TP];  // feats-T -> out-T -> newinst-T
    __shared__ __align__(8) float bufB[ED][TP];  // inst-T (old)
    __shared__ float sHW[ED*ADIM + ED*NCLS + ED];

    for (int idx = t; idx < TR*ED; idx += 256) {
        int r = idx >> 8, col = idx & 255;
        int row = r0 + r;
        bufA[col][r] = (row < NA) ? feats[row*ED + col] : 0.f;
        bufB[col][r] = (row < NA) ? inst[row*ED + col]  : 0.f;
    }
    for (int idx = t; idx < ED*ADIM; idx += 256) sHW[idx] = reg_w[idx];
    bool do_cls = (cls_mode != 0);
    if (do_cls)
        for (int idx = t; idx < ED*NCLS; idx += 256) sHW[ED*ADIM + idx] = cls_w[idx];
    if (qt_on)
        for (int idx = t; idx < ED; idx += 256) sHW[ED*ADIM + ED*NCLS + idx] = qt_w[idx];
    __syncthreads();

    // ---- phase A: out = feats @ outp_w + b ----
    ull accA[4] = {0ull,0ull,0ull,0ull};
    for (int k = 0; k < ED; k++) {
        float wv = outp_w[k*ED + t];
        ull wd = pack2(wv, wv);
        #pragma unroll
        for (int p = 0; p < 4; p++) {
            ull b = *(const ull*)&bufA[k][2*p];
            ffma2(accA[p], wd, b);
        }
    }
    __syncthreads();   // all reads of bufA done before overwrite
    {
        float ob = outp_b[t];
        #pragma unroll
        for (int p = 0; p < 4; p++) {
            float x, y;
            unpack2(accA[p], x, y);
            bufA[t][2*p]   = x + ob;
            bufA[t][2*p+1] = y + ob;
        }
    }
    __syncthreads();

    // ---- phase B: newinst = relu([out|inst] @ ffn_w + b) ----
    ull accB[4] = {0ull,0ull,0ull,0ull};
    for (int k = 0; k < ED; k++) {
        float wv = ffn_w[k*ED + t];
        ull wd = pack2(wv, wv);
        #pragma unroll
        for (int p = 0; p < 4; p++) {
            ull b = *(const ull*)&bufA[k][2*p];
            ffma2(accB[p], wd, b);
        }
    }
    for (int k = 0; k < ED; k++) {
        float wv = ffn_w[(ED + k)*ED + t];
        ull wd = pack2(wv, wv);
        #pragma unroll
        for (int p = 0; p < 4; p++) {
            ull b = *(const ull*)&bufB[k][2*p];
            ffma2(accB[p], wd, b);
        }
    }
    __syncthreads();   // bufA reads done
    {
        float fb = ffn_b[t];
        #pragma unroll
        for (int p = 0; p < 4; p++) {
            float x, y;
            unpack2(accB[p], x, y);
            x = fmaxf(x + fb, 0.f);
            y = fmaxf(y + fb, 0.f);
            bufA[t][2*p]   = x;
            bufA[t][2*p+1] = y;
            int rowx = r0 + 2*p, rowy = r0 + 2*p + 1;
            if (rowx < NA) inst[rowx*ED + t] = x;
            if (rowy < NA) inst[rowy*ED + t] = y;
        }
    }
    __syncthreads();

    // ---- heads ----
    float ti = time_interval[0];
    for (int o = t; o < TR*ADIM; o += 256) {
        int r = o / ADIM, j = o % ADIM;
        int row = r0 + r;
        if (row < NA) {
            float s = reg_b[j];
            for (int k = 0; k < ED; k++) s += bufA[k][r] * sHW[k*ADIM + j];
            if (j >= 8) s /= ti;
            anch[row*ADIM + j] += s;
        }
    }
    if (do_cls) {
        float* cdst = (cls_mode == 1) ? g_cls : cls_dst;
        for (int o = t; o < TR*NCLS; o += 256) {
            int r = o / NCLS, j = o % NCLS;
            int row = r0 + r;
            if (row < NA) {
                float s = cls_b[j];
                for (int k = 0; k < ED; k++) s += bufA[k][r] * sHW[ED*ADIM + k*NCLS + j];
                cdst[row*NCLS + j] = s;
            }
        }
    }
    if (qt_on) {
        for (int o = t; o < TR; o += 256) {
            int row = r0 + o;
            if (row < NA) {
                float s = qt_b[0];
                for (int k = 0; k < ED; k++) s += bufA[k][o] * sHW[ED*ADIM + ED*NCLS + k];
                qt_dst[row] = s;
            }
        }
    }
}

// ===================== rank + gather ===============
__global__ void k_rank()
{
    __shared__ float ssc[NA];
    int t = threadIdx.x;
    if (t < NA) {
        float m = -1e30f;
        #pragma unroll
        for (int j = 0; j < NCLS; j++) m = fmaxf(m, g_cls[t*NCLS + j]);
        ssc[t] = m;
    }
    __syncthreads();
    if (t < NA) {
        float sc = ssc[t];
        int cnt = 0;
        for (int b = 0; b < NA; b++) {
            float sb = ssc[b];
            cnt += (sb > sc) || (sb == sc && b < t);
        }
        if (cnt < NSEL) g_sel[NTEMP + cnt] = t;
    }
}

__global__ void k_gather(const float* __restrict__ temp_inst,
                         const float* __restrict__ temp_anchor,
                         const unsigned char* __restrict__ mask)
{
    int r = blockIdx.x, t = threadIdx.x;
    bool m = mask[0] != 0;
    if (m) {
        if (r < NTEMP) {
            g_instB[r*ED + t] = temp_inst[r*ED + t];
            if (t < ADIM) g_anchorB[r*ADIM + t] = temp_anchor[r*ADIM + t];
        } else {
            int s = g_sel[r];
            g_instB[r*ED + t] = g_instA[s*ED + t];
            if (t < ADIM) g_anchorB[r*ADIM + t] = g_anchorA[s*ADIM + t];
        }
    } else {
        g_instB[r*ED + t] = g_instA[r*ED + t];
        if (t < ADIM) g_anchorB[r*ADIM + t] = g_anchorA[r*ADIM + t];
    }
}

// ===================== finalize ===========================================
__global__ void k_finalize(float* __restrict__ out,
                           const int* __restrict__ track_id,
                           const unsigned char* __restrict__ mask)
{
    int i = blockIdx.x*blockDim.x + threadIdx.x;
    if (i < NA*ED)   out[OFF_INST + i]   = g_instB[i];
    if (i < NA*ADIM) out[OFF_ANCHOR + i] = g_anchorB[i];
    if (i < NA) {
        bool m = mask[0] != 0;
        out[OFF_TRACK + i] = m ? (float)track_id[i] : -1.0f;
    }
}

// ===================== host ===============================================
extern "C" void kernel_launch(void* const* d_in, const int* in_sizes, int n_in,
                              void* d_out, int out_size)
{
    const float* feature      = (const float*)d_in[0];
    const int*   ss           = (const int*)d_in[1];
    const int*   lsi          = (const int*)d_in[2];
    const float* inst_in      = (const float*)d_in[3];
    const float* anchor_in    = (const float*)d_in[4];
    const float* ti           = (const float*)d_in[5];
    const float* temp_inst    = (const float*)d_in[6];
    const float* temp_anchor  = (const float*)d_in[7];
    const unsigned char* mask = (const unsigned char*)d_in[8];
    const int*   track_id     = (const int*)d_in[9];
    const float* image_wh     = (const float*)d_in[10];
    const float* l2i          = (const float*)d_in[11];
    const float* anchor_w     = (const float*)d_in[12];
    const float* anchor_b     = (const float*)d_in[13];
    const float* kps_w        = (const float*)d_in[14];
    const float* kps_b        = (const float*)d_in[15];
    const float* wfc_w        = (const float*)d_in[16];
    const float* wfc_b        = (const float*)d_in[17];
    const float* outp_w       = (const float*)d_in[18];
    const float* outp_b       = (const float*)d_in[19];
    const float* ffn_w        = (const float*)d_in[20];
    const float* ffn_b        = (const float*)d_in[21];
    const float* reg_w        = (const float*)d_in[22];
    const float* reg_b        = (const float*)d_in[23];
    const float* cls_w        = (const float*)d_in[24];
    const float* cls_b        = (const float*)d_in[25];
    const float* qt_w         = (const float*)d_in[26];
    const float* qt_b         = (const float*)d_in[27];

    int T = in_sizes[0] / (NC*ED);
    float* out = (float*)d_out;

    k_init<<<(NA*ED + 255)/256, 256>>>(inst_in, anchor_in);

    for (int i = 0; i < NDEC; i++) {
        int use_b = (i >= 1) ? 1 : 0;

        k1_embed_kps_proj<<<NA, 256>>>(anchor_w, anchor_b,
                                       kps_w + (size_t)i*ED*NLEARN*3,
                                       kps_b + (size_t)i*NLEARN*3,
                                       l2i, image_wh, use_b);

        dim3 g2(WTOT/BN, (NA + BM - 1)/BM);
        k2_wfc_gemm<<<g2, 256>>>(wfc_w + (size_t)i*ED*WTOT,
                                 wfc_b + (size_t)i*WTOT, use_b);

        float* feats = out + OFF_TMP + (size_t)i*NA*ED;
        k4_daf<<<NA, 256>>>(feature, ss, lsi, T, feats);

        int cls_mode = (i == 0) ? 1 : ((i == NDEC-1) ? 2 : 0);
        int qt_on    = (i == NDEC-1) ? 1 : 0;
        k5_tail<<<(NA + TR - 1)/TR, 256>>>(feats,
                    outp_w + (size_t)i*ED*ED,    outp_b + (size_t)i*ED,
                    ffn_w  + (size_t)i*2*ED*ED,  ffn_b  + (size_t)i*ED,
                    reg_w  + (size_t)i*ED*ADIM,  reg_b  + (size_t)i*ADIM,
                    cls_w  + (size_t)i*ED*NCLS,  cls_b  + (size_t)i*NCLS,
                    qt_w   + (size_t)i*ED,       qt_b   + (size_t)i,
                    ti, use_b, cls_mode, out + OFF_CLS, qt_on, out + OFF_QT);

        if (i == 0) {
            k_rank<<<1, 1024>>>();
            k_gather<<<NA, 256>>>(temp_inst, temp_anchor, mask);
        }
    }

    k_finalize<<<(NA*ED + 255)/256, 256>>>(out, track_id, mask);
}